// round 10
// baseline (speedup 1.0000x reference)
#include <cuda_runtime.h>
#include <cstdint>

// Problem dims
#define B_   512
#define T_   1024
#define D_   64
#define H_   256
#define O_   64
#define KTOT 320           // combined [x(64) | h(256)]

#define ROWS 4
#define NCTA (B_/ROWS)     // 128
#define NTHR 512
#define KBN  4             // k-slices
#define KSL  80            // k per slice
#define VS4  84            // padded slice stride (floats): kb offsets {0,80,32,112} mod 128
#define RSTR (KBN*VS4)     // 336 floats per row
#define VBUF (ROWS*RSTR)   // 1344 floats (single buffer)

typedef unsigned long long ull;

// Per-thread W: 2 j x 80 k = 160 floats = 80 ull = 2 jj x 40 k-pairs (kp)
//   kp  0..11 -> registers  (g_Wr,  24 ull/thread)
//   kp 12..35 -> SMEM       (g_Ws,  24 ulonglong2/thread)
//   kp 36..39 -> L2 stream  (g_Wl,   4 ulonglong2/thread)
__device__ ull        g_Wr[24*NTHR];
__device__ ulonglong2 g_Ws[24*NTHR];
__device__ ulonglong2 g_Wl[4*NTHR];

__device__ __forceinline__ ull fma2(ull a, ull b, ull c) {
    ull d; asm("fma.rn.f32x2 %0, %1, %2, %3;" : "=l"(d) : "l"(a), "l"(b), "l"(c));
    return d;
}
__device__ __forceinline__ ull add2(ull a, ull b) {
    ull d; asm("add.rn.f32x2 %0, %1, %2;" : "=l"(d) : "l"(a), "l"(b));
    return d;
}

// Pack Wf[H, D+H] into the three per-thread layouts.
__global__ void ltc_prep(const float* __restrict__ Wf) {
    int idx = blockIdx.x * blockDim.x + threadIdx.x;
    if (idx >= 80*NTHR) return;
    int tid = idx & (NTHR-1);
    int p   = idx >> 9;            // 0..79
    int jj  = p / 40, kp = p % 40;
    int warp = tid >> 5, lane = tid & 31;
    int kb = lane & 3;
    int g  = warp * 8 + (lane >> 2);   // 0..127
    int j  = 2*g + jj;
    int k  = kb*KSL + 2*kp;
    float lo = Wf[j*KTOT + k];
    float hi = Wf[j*KTOT + k + 1];
    ull val = ((ull)__float_as_uint(hi) << 32) | __float_as_uint(lo);
    if (kp < 12) {
        g_Wr[(jj*12 + kp)*NTHR + tid] = val;
    } else if (kp < 36) {
        int u = kp - 12;                 // 0..23
        int e = (u >> 1)*2 + jj;         // entry for (q = 6+u/2, jj)
        ((ull*)g_Ws)[(e*NTHR + tid)*2 + (u & 1)] = val;
    } else {
        int m = kp - 36;                 // 0..3
        int s = (m >> 1)*2 + jj;         // q18 -> {0,1}, q19 -> {2,3}
        ((ull*)g_Wl)[(s*NTHR + tid)*2 + (m & 1)] = val;
    }
}

// SMEM: s_w 24*512 ulonglong2 (196608 B) | s_v 1344 f (5376 B) | s_z 1024 ull (8192 B)
#define SM_V   (24*NTHR*4)                 // float index of s_v
#define SM_Z   (SM_V + VBUF)
#define SM_TOT (SM_Z + 2048)               // 52,544 floats = 210,176 B

__global__ __launch_bounds__(NTHR, 1)
void ltc_main(const float* __restrict__ x,
              const float* __restrict__ bf,
              const float* __restrict__ tau,
              const float* __restrict__ A,
              const float* __restrict__ Wo,
              const float* __restrict__ bo,
              float* __restrict__ out)
{
    extern __shared__ float sm[];
    ulonglong2* s_w = (ulonglong2*)sm;
    float*      s_v = sm + SM_V;
    ull*        s_z = (ull*)(sm + SM_Z);

    const int tid  = threadIdx.x;
    const int lane = tid & 31;
    const int kb   = lane & 3;
    const int g    = (tid >> 5)*8 + (lane >> 2);  // 0..127
    const int row0 = blockIdx.x * ROWS;

    // ---- stage SMEM-W (coalesced) ----
    for (int e = 0; e < 24; e++) s_w[e*NTHR + tid] = g_Ws[e*NTHR + tid];

    // ---- W registers ----
    ull w2[24];
#pragma unroll
    for (int p = 0; p < 24; p++) w2[p] = g_Wr[p*NTHR + tid];

    // ---- updater state: thread handles (uj, rows rr and rr+2) ----
    const int uj = tid & 255;
    const int rr = tid >> 8;
    const float bfj = bf[uj];
    const float itj = expf(-tau[uj]);
    const float Aj  = A[uj];
    float h_a = 0.f, h_b = 0.f;
    const int hk   = 64 + uj;
    const int hadr = (hk/KSL)*VS4 + (hk % KSL);

    // ---- x writer (threads < 256) ----
    const int xr = (tid >> 6) & 3, xd = tid & 63;
    const float* xptr = x + (size_t)(row0 + xr) * T_ * D_ + xd;

    // ---- init v: zeros, then x(t=0) ----
    for (int i = tid; i < VBUF; i += NTHR) s_v[i] = 0.f;
    __syncthreads();
    if (tid < 256) s_v[xr*RSTR + xd] = xptr[0];
    __syncthreads();

    const float* vbk = s_v + kb*VS4;

    // ================= recurrent loop =================
    for (int t = 0; t < T_; ++t) {
        // L2 ring wave A (consumed at q=18, ~2000 cyc later)
        ulonglong2 rA0 = g_Wl[0*NTHR + tid];
        ulonglong2 rA1 = g_Wl[1*NTHR + tid];

        float x_pre = 0.f;
        if (tid < 256 && t + 1 < T_) x_pre = xptr[(t + 1) * D_];

        ull acc[8];
#pragma unroll
        for (int i = 0; i < 8; i++) acc[i] = 0ull;

#define ROWS_FMA(WA0,WB0,WA1,WB1)                                         \
        {                                                                  \
            ulonglong2 v0 = *(const ulonglong2*)(vbk + 0*RSTR + 4*q);      \
            ulonglong2 v1 = *(const ulonglong2*)(vbk + 1*RSTR + 4*q);      \
            ulonglong2 v2 = *(const ulonglong2*)(vbk + 2*RSTR + 4*q);      \
            ulonglong2 v3 = *(const ulonglong2*)(vbk + 3*RSTR + 4*q);      \
            acc[0] = fma2(WA0, v0.x, acc[0]); acc[0] = fma2(WB0, v0.y, acc[0]); \
            acc[1] = fma2(WA0, v1.x, acc[1]); acc[1] = fma2(WB0, v1.y, acc[1]); \
            acc[2] = fma2(WA0, v2.x, acc[2]); acc[2] = fma2(WB0, v2.y, acc[2]); \
            acc[3] = fma2(WA0, v3.x, acc[3]); acc[3] = fma2(WB0, v3.y, acc[3]); \
            acc[4] = fma2(WA1, v0.x, acc[4]); acc[4] = fma2(WB1, v0.y, acc[4]); \
            acc[5] = fma2(WA1, v1.x, acc[5]); acc[5] = fma2(WB1, v1.y, acc[5]); \
            acc[6] = fma2(WA1, v2.x, acc[6]); acc[6] = fma2(WB1, v2.y, acc[6]); \
            acc[7] = fma2(WA1, v3.x, acc[7]); acc[7] = fma2(WB1, v3.y, acc[7]); \
        }

        // ---- q 0..5: W from registers ----
#pragma unroll
        for (int q = 0; q < 6; q++) {
            ROWS_FMA(w2[2*q], w2[2*q+1], w2[12+2*q], w2[12+2*q+1]);
        }

        // ---- q 6..11: W from SMEM ----
#pragma unroll
        for (int q = 6; q < 12; q++) {
            ulonglong2 wj0 = s_w[((q-6)*2 + 0)*NTHR + tid];
            ulonglong2 wj1 = s_w[((q-6)*2 + 1)*NTHR + tid];
            ROWS_FMA(wj0.x, wj0.y, wj1.x, wj1.y);
        }

        // L2 ring wave B (consumed at q=19)
        ulonglong2 rB0 = g_Wl[2*NTHR + tid];
        ulonglong2 rB1 = g_Wl[3*NTHR + tid];

        // ---- q 12..17: W from SMEM ----
#pragma unroll
        for (int q = 12; q < 18; q++) {
            ulonglong2 wj0 = s_w[((q-6)*2 + 0)*NTHR + tid];
            ulonglong2 wj1 = s_w[((q-6)*2 + 1)*NTHR + tid];
            ROWS_FMA(wj0.x, wj0.y, wj1.x, wj1.y);
        }

        // ---- q 18,19: W from L2 ring ----
        { const int q = 18; ROWS_FMA(rA0.x, rA0.y, rA1.x, rA1.y); }
        { const int q = 19; ROWS_FMA(rB0.x, rB0.y, rB1.x, rB1.y); }
#undef ROWS_FMA

        // ---- butterfly over the 4 kb lanes ----
#pragma unroll
        for (int d = 1; d < 4; d <<= 1) {
#pragma unroll
            for (int i = 0; i < 8; i++)
                acc[i] = add2(acc[i], __shfl_xor_sync(0xFFFFFFFFu, acc[i], d));
        }

        // all lanes post: lane's kb picks the row it publishes
        s_z[kb*256 + 2*g + 0] = acc[0*4 + kb];
        s_z[kb*256 + 2*g + 1] = acc[1*4 + kb];
        __syncthreads();

        // ---- gate + state update ----
        {
            ull za = s_z[rr*256 + uj];
            ull zb = s_z[(rr+2)*256 + uj];
            float zA = __uint_as_float((unsigned)za)
                     + __uint_as_float((unsigned)(za >> 32)) + bfj;
            float zB = __uint_as_float((unsigned)zb)
                     + __uint_as_float((unsigned)(zb >> 32)) + bfj;
            float fA = __fdividef(1.f, 1.f + __expf(-zA));
            float fB = __fdividef(1.f, 1.f + __expf(-zB));
            h_a += (-(itj + fA) * h_a + fA * Aj) * 0.1f;
            h_b += (-(itj + fB) * h_b + fB * Aj) * 0.1f;
            s_v[rr*RSTR + hadr]     = h_a;
            s_v[(rr+2)*RSTR + hadr] = h_b;
            if (tid < 256) s_v[xr*RSTR + xd] = x_pre;
        }
        __syncthreads();
    }

    // ================= output projection =================
    float* s_hl = (float*)s_z;            // [r][j]
    s_hl[rr*256 + uj]     = h_a;
    s_hl[(rr+2)*256 + uj] = h_b;
    float* s_wo = (float*)s_w;            // reuse W region: [o][260]
    __syncthreads();
    for (int i = tid; i < 64*256; i += NTHR) {
        int o = i >> 8, q = i & 255;
        s_wo[o*260 + q] = Wo[i];
    }
    __syncthreads();

    if (tid < 256) {
        int r = tid >> 6, o = tid & 63;
        const float4* w4 = (const float4*)(s_wo + o*260);
        const float4* h4 = (const float4*)(s_hl + r*256);
        float s = bo[o];
#pragma unroll
        for (int q = 0; q < 64; q++) {
            float4 w = w4[q];
            float4 h = h4[q];
            s += w.x*h.x + w.y*h.y + w.z*h.z + w.w*h.w;
        }
        out[(row0 + r)*O_ + o] = s;
    }
}

extern "C" void kernel_launch(void* const* d_in, const int* in_sizes, int n_in,
                              void* d_out, int out_size)
{
    (void)in_sizes; (void)n_in; (void)out_size;
    const float* x   = (const float*)d_in[0];
    const float* Wf  = (const float*)d_in[1];
    const float* bf  = (const float*)d_in[2];
    const float* tau = (const float*)d_in[3];
    const float* A   = (const float*)d_in[4];
    const float* Wo  = (const float*)d_in[5];
    const float* bo  = (const float*)d_in[6];
    float* out = (float*)d_out;

    const int smem_bytes = SM_TOT * (int)sizeof(float);  // 210,176 B
    cudaFuncSetAttribute(ltc_main,
                         cudaFuncAttributeMaxDynamicSharedMemorySize, smem_bytes);

    ltc_prep<<<(80*NTHR + NTHR - 1) / NTHR, NTHR>>>(Wf);
    ltc_main<<<NCTA, NTHR, smem_bytes>>>(x, bf, tau, A, Wo, bo, out);
}